// round 14
// baseline (speedup 1.0000x reference)
#include <cuda_runtime.h>
#include <math.h>

#define Dn 384
#define Nn 96
#define TPB 256
#define FULLMASK 0xffffffffu

// Per-site chain vectors w_j = C_{j-1} v_j (current epoch), L2-resident.
__device__ float whist_g[Dn][Nn];

// Dynamic shared memory (~152 KB).
struct Smem {
    float P[Dn * Nn];                 // eigfunc[:, :96] row-major [site][comp]
    float qarr[Dn];                   // per-site pivot complement q (cur epoch)
    float probs[Dn];                  // window probs (current step)
    float cdfa[Dn];                   // running cdf (current step)
    __align__(16) float w[2][2 * Nn]; // heavy: [buf][ w1(96) | w2(96) ]
    __align__(16) float qpb[2][96];   // heavy: [buf][ q1p | sp | q2p ] x32
    __align__(16) float gfin[Nn];     // light: final correction vector
    float delta_s;
    float runF_s, cdfF_s;             // light: run/cdf carried to F
    float arl_s, cdfl_s, cdfs_s;      // loose/strict exit records
    int   jl_s, js_s, exl_s, exs_s;
    int   cnt[8];
};

__device__ __forceinline__ float grcp(float x) {
    return (fabsf(x) > 1e-30f) ? __frcp_rn(x) : 0.0f;
}

__device__ __forceinline__ void load12(const float* src, float d[12]) {
    const float4* s4 = reinterpret_cast<const float4*>(src);
    float4 a = s4[0], b = s4[1], c = s4[2];
    d[0]=a.x; d[1]=a.y; d[2]=a.z; d[3]=a.w;
    d[4]=b.x; d[5]=b.y; d[6]=b.z; d[7]=b.w;
    d[8]=c.x; d[9]=c.y; d[10]=c.z; d[11]=c.w;
}

// Deterministic fixed-order sum of 32 floats (16B-aligned smem).
__device__ __forceinline__ float sum32(const float* q) {
    const float4* q4 = reinterpret_cast<const float4*>(q);
    float t[8];
#pragma unroll
    for (int i = 0; i < 8; i++) {
        float4 v = q4[i];
        t[i] = (v.x + v.y) + (v.z + v.w);
    }
    return ((t[0]+t[1]) + (t[2]+t[3])) + ((t[4]+t[5]) + (t[6]+t[7]));
}

// Balanced 12-term dot (4 accumulators), fixed order.
__device__ __forceinline__ float dot12(const float* c, const float v[12]) {
    float a = c[0]*v[0]; a = fmaf(c[4], v[4], a); a = fmaf(c[8],  v[8],  a);
    float b = c[1]*v[1]; b = fmaf(c[5], v[5], b); b = fmaf(c[9],  v[9],  b);
    float d = c[2]*v[2]; d = fmaf(c[6], v[6], d); d = fmaf(c[10], v[10], d);
    float e = c[3]*v[3]; e = fmaf(c[7], v[7], e); e = fmaf(c[11], v[11], e);
    return (a + b) + (d + e);
}

__device__ __forceinline__ float bfly5(float a) {
#pragma unroll
    for (int off = 16; off; off >>= 1)
        a += __shfl_xor_sync(FULLMASK, a, off);
    return a;
}

// ---------------------------------------------------------------------------
// Light pass (warp 0 only; lane l owns components 3l..3l+2).
// Epoch change = exactly rank-1: D = delta * g g^T, seeded by flipping site
// `pos` from empty-conditioned to occupied:
//   delta0 = -(1/q_pos + 1/(1-q_pos)),  g0 = w_pos  (stored, current epoch).
// Per-site recursion (division-free in computed dots):
//   e = g.v ; c = delta*e ; q' = q + e*c ; w' = w + c*g ;
//   g <- g + (e * grcp(1-q)) * w ; delta <- delta*(1-q)*grcp(1-q')
// QUAD BATCHING: e_s linear in 10 pre-reducible dots (g.v_s, w_i.v_s i<s)
// -> ONE butterfly round per 4 sites. Refreshes ALL of [xmin, F); tracks BOTH
// loose and strict exits (thresholds identical to the R13-passing version).
// ---------------------------------------------------------------------------
__device__ void light_pass(Smem* __restrict__ sm, int xmin, int F, int pos,
                           float uk)
{
    const int l  = threadIdx.x & 31;
    const int b0 = 3 * l;
    float g0 = whist_g[pos][b0+0];
    float g1 = whist_g[pos][b0+1];
    float g2 = whist_g[pos][b0+2];
    const float qp = sm->qarr[pos];
    float delta = -(grcp(qp) + grcp(1.0f - qp));
    float run = 1.0f, cdf = 0.0f;
    int exl = 0, jl = F, exs = 0, js = F;
    float arl = 0.0f, cdfl = 0.0f, cdfs = 0.0f;
    int j = xmin;

    // double-buffered quad data (w rows, old q, old inv-pivot)
    float wq[2][4][3], qq[2][4], ipq[2][4];
    int cur = 0;
    if (j + 3 < F) {
#pragma unroll
        for (int s = 0; s < 4; s++) {
            wq[0][s][0] = whist_g[j+s][b0+0];
            wq[0][s][1] = whist_g[j+s][b0+1];
            wq[0][s][2] = whist_g[j+s][b0+2];
            qq[0][s]  = sm->qarr[j+s];
            ipq[0][s] = grcp(1.0f - qq[0][s]);
        }
    }

    while (j + 3 < F) {
        const int nxt = cur ^ 1;
        if (j + 7 < F) {   // prefetch next quad
#pragma unroll
            for (int s = 0; s < 4; s++) {
                wq[nxt][s][0] = whist_g[j+4+s][b0+0];
                wq[nxt][s][1] = whist_g[j+4+s][b0+1];
                wq[nxt][s][2] = whist_g[j+4+s][b0+2];
                qq[nxt][s]  = sm->qarr[j+4+s];
                ipq[nxt][s] = grcp(1.0f - qq[nxt][s]);
            }
        }
        float v[4][3];
#pragma unroll
        for (int s = 0; s < 4; s++) {
            const float* vp = &sm->P[(j+s) * Nn + b0];
            v[s][0] = vp[0]; v[s][1] = vp[1]; v[s][2] = vp[2];
        }
        float (&w)[4][3] = wq[cur];

        // 10 partial dots
        float d[10];
        d[0] = g0*v[0][0] + g1*v[0][1] + g2*v[0][2];           // g.v0
        d[1] = g0*v[1][0] + g1*v[1][1] + g2*v[1][2];           // g.v1
        d[2] = g0*v[2][0] + g1*v[2][1] + g2*v[2][2];           // g.v2
        d[3] = g0*v[3][0] + g1*v[3][1] + g2*v[3][2];           // g.v3
        d[4] = w[0][0]*v[1][0] + w[0][1]*v[1][1] + w[0][2]*v[1][2];  // w0.v1
        d[5] = w[0][0]*v[2][0] + w[0][1]*v[2][1] + w[0][2]*v[2][2];  // w0.v2
        d[6] = w[0][0]*v[3][0] + w[0][1]*v[3][1] + w[0][2]*v[3][2];  // w0.v3
        d[7] = w[1][0]*v[2][0] + w[1][1]*v[2][1] + w[1][2]*v[2][2];  // w1.v2
        d[8] = w[1][0]*v[3][0] + w[1][1]*v[3][1] + w[1][2]*v[3][2];  // w1.v3
        d[9] = w[2][0]*v[3][0] + w[2][1]*v[3][1] + w[2][2]*v[3][2];  // w2.v3
        // one butterfly round for all 10 values
#pragma unroll
        for (int off = 16; off; off >>= 1) {
#pragma unroll
            for (int i = 0; i < 10; i++)
                d[i] += __shfl_xor_sync(FULLMASK, d[i], off);
        }

        // e/t chain (uses only precomputed old-pivot reciprocals)
        const float e0 = d[0];                               const float t0 = e0 * ipq[cur][0];
        const float e1 = d[1] + t0*d[4];                     const float t1 = e1 * ipq[cur][1];
        const float e2 = d[2] + t0*d[5] + t1*d[7];           const float t2 = e2 * ipq[cur][2];
        const float e3 = d[3] + t0*d[6] + t1*d[8] + t2*d[9]; const float t3 = e3 * ipq[cur][3];

        // delta/q chain
        const float c0 = delta*e0; const float q0n = qq[cur][0] + e0*c0;
        delta = delta * (1.0f - qq[cur][0]) * grcp(1.0f - q0n);
        const float c1 = delta*e1; const float q1n = qq[cur][1] + e1*c1;
        delta = delta * (1.0f - qq[cur][1]) * grcp(1.0f - q1n);
        const float c2 = delta*e2; const float q2n = qq[cur][2] + e2*c2;
        delta = delta * (1.0f - qq[cur][2]) * grcp(1.0f - q2n);
        const float c3 = delta*e3; const float q3n = qq[cur][3] + e3*c3;
        delta = delta * (1.0f - qq[cur][3]) * grcp(1.0f - q3n);

        // vector updates + stores: w'_s = w_s + c_s*g_s, then g advances
        whist_g[j][b0+0] = w[0][0] + c0*g0;
        whist_g[j][b0+1] = w[0][1] + c0*g1;
        whist_g[j][b0+2] = w[0][2] + c0*g2;
        g0 += t0*w[0][0]; g1 += t0*w[0][1]; g2 += t0*w[0][2];
        whist_g[j+1][b0+0] = w[1][0] + c1*g0;
        whist_g[j+1][b0+1] = w[1][1] + c1*g1;
        whist_g[j+1][b0+2] = w[1][2] + c1*g2;
        g0 += t1*w[1][0]; g1 += t1*w[1][1]; g2 += t1*w[1][2];
        whist_g[j+2][b0+0] = w[2][0] + c2*g0;
        whist_g[j+2][b0+1] = w[2][1] + c2*g1;
        whist_g[j+2][b0+2] = w[2][2] + c2*g2;
        g0 += t2*w[2][0]; g1 += t2*w[2][1]; g2 += t2*w[2][2];
        whist_g[j+3][b0+0] = w[3][0] + c3*g0;
        whist_g[j+3][b0+1] = w[3][1] + c3*g1;
        whist_g[j+3][b0+2] = w[3][2] + c3*g2;
        g0 += t3*w[3][0]; g1 += t3*w[3][1]; g2 += t3*w[3][2];

        // exact renormalization: delta*2^24, g*2^-12 (fp-exact)
        if (fabsf(delta) < 1e-10f && delta != 0.0f) {
            delta *= 16777216.0f;
            g0 *= 2.44140625e-4f; g1 *= 2.44140625e-4f; g2 *= 2.44140625e-4f;
        }

        // bookkeeping (replicated scalars; lane 0 writes) — always to F
        const float qn[4] = {q0n, q1n, q2n, q3n};
#pragma unroll
        for (int s = 0; s < 4; s++) {
            float prob = run * qn[s];
            if (!(fabsf(prob) > 1e-15f)) prob = 0.0f;
            cdf += prob;
            run *= (1.0f - qn[s]);
            if (l == 0) { sm->probs[j+s] = prob; sm->cdfa[j+s] = cdf; }
            const float ar = fabsf(run);
            if (!exs && ar < 3e-9f * cdf) { exs = 1; js = j + s + 1; cdfs = cdf; }
            if (!exl && (uk * (cdf + ar) < cdf * (1.0f - 1e-4f)) &&
                (ar < 3e-4f * cdf)) { exl = 1; jl = j + s + 1; arl = ar; cdfl = cdf; }
            if (l == 0) sm->qarr[j+s] = qn[s];
        }

        j += 4; cur ^= 1;
    }

    // tail: single-site path (<= 3 sites), loads directly
    while (j < F) {
        const float w0 = whist_g[j][b0+0];
        const float w1 = whist_g[j][b0+1];
        const float w2 = whist_g[j][b0+2];
        const float qa = sm->qarr[j];
        const float* vp = &sm->P[j * Nn + b0];
        float e = g0*vp[0] + g1*vp[1] + g2*vp[2];
        e = bfly5(e);
        const float c  = delta * e;
        const float qn = qa + e * c;
        whist_g[j][b0+0] = w0 + c*g0;
        whist_g[j][b0+1] = w1 + c*g1;
        whist_g[j][b0+2] = w2 + c*g2;
        const float t = e * grcp(1.0f - qa);
        g0 += t*w0; g1 += t*w1; g2 += t*w2;
        delta = delta * (1.0f - qa) * grcp(1.0f - qn);
        float prob = run * qn;
        if (!(fabsf(prob) > 1e-15f)) prob = 0.0f;
        cdf += prob;
        run *= (1.0f - qn);
        if (l == 0) { sm->probs[j] = prob; sm->cdfa[j] = cdf; }
        const float ar = fabsf(run);
        if (!exs && ar < 3e-9f * cdf) { exs = 1; js = j + 1; cdfs = cdf; }
        if (!exl && (uk * (cdf + ar) < cdf * (1.0f - 1e-4f)) &&
            (ar < 3e-4f * cdf)) { exl = 1; jl = j + 1; arl = ar; cdfl = cdf; }
        if (l == 0) sm->qarr[j] = qn;
        j++;
    }

    // publish correction + scan scalars
    sm->gfin[b0+0] = g0; sm->gfin[b0+1] = g1; sm->gfin[b0+2] = g2;
    if (l == 0) {
        sm->delta_s = delta;
        sm->runF_s = run;  sm->cdfF_s = cdf;
        sm->exl_s = exl; sm->jl_s = jl; sm->arl_s = arl; sm->cdfl_s = cdfl;
        sm->exs_s = exs; sm->js_s = js; sm->cdfs_s = cdfs;
    }
}

// ---------------------------------------------------------------------------
// Heavy scan produce helpers (frontier sites; full matvec + reductions).
// Tiling: rt = tid>>3 (rows 3rt..3rt+2), ct = tid&7 (cols 12ct..12ct+11).
// ---------------------------------------------------------------------------
__device__ __forceinline__ void produce1(Smem* __restrict__ sm,
                                         const float C[3][12], float p1[3],
                                         int j, int buf, int rt, int ct)
{
    float v[12];
    load12(&sm->P[j * Nn + 12 * ct], v);
    p1[0] = dot12(C[0], v);
    p1[1] = dot12(C[1], v);
    p1[2] = dot12(C[2], v);
#pragma unroll
    for (int off = 1; off < 8; off <<= 1) {
        p1[0] += __shfl_xor_sync(FULLMASK, p1[0], off);
        p1[1] += __shfl_xor_sync(FULLMASK, p1[1], off);
        p1[2] += __shfl_xor_sync(FULLMASK, p1[2], off);
    }
    const float* vr = &sm->P[j * Nn + 3 * rt];
    const float qp = vr[0]*p1[0] + vr[1]*p1[1] + vr[2]*p1[2];
    if (ct == 0) {
        sm->w[buf][3*rt+0] = p1[0];
        sm->w[buf][3*rt+1] = p1[1];
        sm->w[buf][3*rt+2] = p1[2];
        sm->qpb[buf][rt] = qp;
    }
}

__device__ __forceinline__ void produce2(Smem* __restrict__ sm,
                                         const float C[3][12],
                                         float p1[3], float p2[3],
                                         int j, int buf, int rt, int ct)
{
    float v1[12], v2[12];
    load12(&sm->P[j * Nn + 12 * ct], v1);
    load12(&sm->P[(j + 1) * Nn + 12 * ct], v2);
#pragma unroll
    for (int a = 0; a < 3; a++) {
        p1[a] = dot12(C[a], v1);
        p2[a] = dot12(C[a], v2);
    }
#pragma unroll
    for (int off = 1; off < 8; off <<= 1) {
        p1[0] += __shfl_xor_sync(FULLMASK, p1[0], off);
        p1[1] += __shfl_xor_sync(FULLMASK, p1[1], off);
        p1[2] += __shfl_xor_sync(FULLMASK, p1[2], off);
        p2[0] += __shfl_xor_sync(FULLMASK, p2[0], off);
        p2[1] += __shfl_xor_sync(FULLMASK, p2[1], off);
        p2[2] += __shfl_xor_sync(FULLMASK, p2[2], off);
    }
    const float* vr1 = &sm->P[j * Nn + 3 * rt];
    const float* vr2 = &sm->P[(j + 1) * Nn + 3 * rt];
    const float q1p = vr1[0]*p1[0] + vr1[1]*p1[1] + vr1[2]*p1[2];
    const float sp  = vr2[0]*p1[0] + vr2[1]*p1[1] + vr2[2]*p1[2];
    const float q2p = vr2[0]*p2[0] + vr2[1]*p2[1] + vr2[2]*p2[2];
    if (ct == 0) {
        sm->w[buf][3*rt+0]    = p1[0];
        sm->w[buf][3*rt+1]    = p1[1];
        sm->w[buf][3*rt+2]    = p1[2];
        sm->w[buf][Nn+3*rt+0] = p2[0];
        sm->w[buf][Nn+3*rt+1] = p2[1];
        sm->w[buf][Nn+3*rt+2] = p2[2];
        sm->qpb[buf][rt]      = q1p;
        sm->qpb[buf][32 + rt] = sp;
        sm->qpb[buf][64 + rt] = q2p;
    }
}

// Heavy frontier scan from jstart with dual stop. Updates run/cdf in place.
// All control scalars replicated across threads (uniform barriers).
__device__ __forceinline__ void heavy_scan(Smem* __restrict__ sm,
    float (&cw)[3][12], int jstart, int xmax, float& run, float& cdf,
    int strict, float uk, int rt, int ct, int tid,
    int& jend_out, int& by_loose_out)
{
    if (jstart >= xmax) { jend_out = jstart; by_loose_out = 0; return; }
    int buf = 0;
    int j = jstart;
    int nb = (xmax - j >= 2) ? 2 : 1;
    float p1[3], p2[3];
    if (nb == 2) produce2(sm, cw, p1, p2, j, buf, rt, ct);
    else         produce1(sm, cw, p1, j, buf, rt, ct);
    for (;;) {
        __syncthreads();
        if (nb == 2) {
            float wc1[12], wc2[12];
            load12(&sm->w[buf][12 * ct], wc1);
            load12(&sm->w[buf][Nn + 12 * ct], wc2);
            const float q1  = sum32(&sm->qpb[buf][0]);
            const float s   = sum32(&sm->qpb[buf][32]);
            const float q2r = sum32(&sm->qpb[buf][64]);
            const float inv1 = grcp(1.0f - q1);
            const float t = inv1 * s;
            const float q2 = q2r + t * s;      // Schur-corrected
            const float inv2 = grcp(1.0f - q2);
            float p2c[3], wc2c[12];
#pragma unroll
            for (int a = 0; a < 3; a++) p2c[a] = p2[a] + t * p1[a];
#pragma unroll
            for (int b = 0; b < 12; b++) wc2c[b] = wc2[b] + t * wc1[b];

            if (ct == 0) {
#pragma unroll
                for (int a = 0; a < 3; a++) {
                    whist_g[j][3*rt+a]   = p1[a];
                    whist_g[j+1][3*rt+a] = p2c[a];
                }
            }
            if (tid == 0) { sm->qarr[j] = q1; sm->qarr[j+1] = q2; }
#pragma unroll
            for (int a = 0; a < 3; a++) {
                const float u1 = p1[a]  * inv1;
                const float u2 = p2c[a] * inv2;
#pragma unroll
                for (int b = 0; b < 12; b++) {
                    cw[a][b] += u1 * wc1[b];
                    cw[a][b] += u2 * wc2c[b];
                }
            }
            float prob = run * q1;
            if (!(fabsf(prob) > 1e-15f)) prob = 0.0f;
            cdf += prob;
            if (tid == 0) { sm->probs[j] = prob; sm->cdfa[j] = cdf; }
            run *= (1.0f - q1);
            prob = run * q2;
            if (!(fabsf(prob) > 1e-15f)) prob = 0.0f;
            cdf += prob;
            if (tid == 0) { sm->probs[j+1] = prob; sm->cdfa[j+1] = cdf; }
            run *= (1.0f - q2);
        } else {
            float wc1[12];
            load12(&sm->w[buf][12 * ct], wc1);
            const float q1 = sum32(&sm->qpb[buf][0]);
            const float inv1 = grcp(1.0f - q1);
            if (ct == 0) {
#pragma unroll
                for (int a = 0; a < 3; a++)
                    whist_g[j][3*rt+a] = p1[a];
            }
            if (tid == 0) sm->qarr[j] = q1;
#pragma unroll
            for (int a = 0; a < 3; a++) {
                const float t = p1[a] * inv1;
#pragma unroll
                for (int b = 0; b < 12; b++) cw[a][b] += t * wc1[b];
            }
            float prob = run * q1;
            if (!(fabsf(prob) > 1e-15f)) prob = 0.0f;
            cdf += prob;
            if (tid == 0) { sm->probs[j] = prob; sm->cdfa[j] = cdf; }
            run *= (1.0f - q1);
        }

        const int jn = j + nb;
        const float ar = fabsf(run);
        const bool stop_s = (ar < 3e-9f * cdf);
        bool stop_l = false;
        if (!strict)
            stop_l = ((uk * (cdf + ar) < cdf * (1.0f - 1e-4f)) &&
                      (ar < 3e-4f * cdf));
        if (stop_s || stop_l || jn >= xmax) {
            jend_out = jn;
            by_loose_out = (stop_l && !stop_s && jn < xmax) ? 1 : 0;
            break;
        }
        const int nb2 = (xmax - jn >= 2) ? 2 : 1;
        if (nb2 == 2) produce2(sm, cw, p1, p2, jn, buf ^ 1, rt, ct);
        else          produce1(sm, cw, p1, jn, buf ^ 1, rt, ct);
        buf ^= 1; j = jn; nb = nb2;
    }
}

__global__ void __launch_bounds__(TPB, 1)
sds_kernel(const float* __restrict__ eig, const float* __restrict__ u,
           float* __restrict__ out)
{
    extern __shared__ unsigned char smraw[];
    Smem* sm = reinterpret_cast<Smem*>(smraw);
    const int tid  = threadIdx.x;
    const int lane = tid & 31;
    const int warp = tid >> 5;
    const int rt   = tid >> 3;   // rows 3rt..3rt+2
    const int ct   = tid & 7;    // cols 12ct..12ct+11

    // Load P = eigfunc[:, :96] (first 96 of each 384-row).
    for (int idx = tid; idx < Dn * Nn; idx += TPB) {
        const int r = idx / Nn, c = idx - r * Nn;
        sm->P[idx] = eig[r * Dn + c];
    }

    // Persistent speculative frontier state cw (all of [0,F) empty). Starts I.
    float cw[3][12];
#pragma unroll
    for (int a = 0; a < 3; a++)
#pragma unroll
        for (int b = 0; b < 12; b++)
            cw[a][b] = (3 * rt + a == 12 * ct + b) ? 1.0f : 0.0f;

    __syncthreads();

    int prev = -1;
    int F = 0;   // frontier: sites [0, F) have current-epoch stored (q, w)
    for (int k = 0; k < Nn; k++) {
        const int xmin = prev + 1;
        const int xmax = Dn - Nn + k + 1;   // exclusive
        const float uk = u[k];

        float runF, cdfF, arl = 0.0f, cdfl = 0.0f, cdfs = 0.0f;
        int exl, exs, jl = F, js = F;

        if (k > 0) {
            if (warp == 0) light_pass(sm, xmin, F, prev, uk);
            __syncthreads();
            // materialize the correction into cw: cw += delta * g g^T
            const float dlt = sm->delta_s;
            const float gr0 = sm->gfin[3*rt+0];
            const float gr1 = sm->gfin[3*rt+1];
            const float gr2 = sm->gfin[3*rt+2];
            float gc[12];
            load12(&sm->gfin[12*ct], gc);
            const float t0 = dlt * gr0, t1 = dlt * gr1, t2 = dlt * gr2;
#pragma unroll
            for (int b = 0; b < 12; b++) {
                cw[0][b] += t0 * gc[b];
                cw[1][b] += t1 * gc[b];
                cw[2][b] += t2 * gc[b];
            }
            runF = sm->runF_s; cdfF = sm->cdfF_s;
            exl = sm->exl_s; jl = sm->jl_s; arl = sm->arl_s; cdfl = sm->cdfl_s;
            exs = sm->exs_s; js = sm->js_s; cdfs = sm->cdfs_s;
        } else {
            runF = 1.0f; cdfF = 0.0f; exl = 0; exs = 0;
        }

        // ---- determine selection window (loose-first, verified) ----
        int jend; float selcdf, selar = 0.0f; int loose;
        int need_heavy, strictm = 0;
        float hrun = runF, hcdf = cdfF;
        const int from_light_loose = exl;
        if (exl)      { jend = jl; selcdf = cdfl; selar = arl; loose = 1; need_heavy = 0; }
        else if (exs) { jend = js; selcdf = cdfs; loose = 0; need_heavy = 0; }
        else          { need_heavy = 1; loose = 0; jend = F; selcdf = cdfF; }

        int pos = -1;
        for (int attempt = 0; attempt < 2; attempt++) {
            if (need_heavy) {
                int je, bl;
                heavy_scan(sm, cw, F, xmax, hrun, hcdf, strictm, uk,
                           rt, ct, tid, je, bl);
                jend = je; F = je;
                selcdf = hcdf; selar = fabsf(hrun); loose = bl;
                need_heavy = 0;
            }
            __syncthreads();   // probs/cdfa visible; orders cnt reuse

            const int len = jend - xmin;        // <= 289 (2 elems/thread)
            if (loose) {
                const float thr_mid = uk * selcdf;
                const float thr_lo  = thr_mid * (1.0f - 3e-6f);
                const float thr_hi  = uk * (selcdf + selar) * (1.0f + 3e-6f);
                int packed = 0;
                if (tid < len) {
                    const float cv = sm->cdfa[xmin + tid];
                    packed += (cv < thr_lo ? 1 : 0)
                            + ((cv < thr_mid ? 1 : 0) << 10)
                            + ((cv < thr_hi ? 1 : 0) << 20);
                }
                if (tid + TPB < len) {
                    const float cv = sm->cdfa[xmin + tid + TPB];
                    packed += (cv < thr_lo ? 1 : 0)
                            + ((cv < thr_mid ? 1 : 0) << 10)
                            + ((cv < thr_hi ? 1 : 0) << 20);
                }
                const int wsum = __reduce_add_sync(FULLMASK, packed);
                if (lane == 0) sm->cnt[warp] = wsum;
                __syncthreads();
                int tot = 0;
#pragma unroll
                for (int i = 0; i < 8; i++) tot += sm->cnt[i];
                const int c_lo  = tot & 1023;
                const int c_hi  = (tot >> 20) & 1023;
                int p_lo = xmin + c_lo;  if (p_lo > jend - 1) p_lo = jend - 1;
                int p_hi = xmin + c_hi;  if (p_hi > jend - 1) p_hi = jend - 1;
                if (p_lo == p_hi) { pos = p_lo; break; }
                // ambiguous: fall back to strict
                if (from_light_loose && exs) {
                    jend = js; selcdf = cdfs; loose = 0; need_heavy = 0;
                } else {
                    // resume heavy with strict stop (hrun/hcdf hold state at F)
                    need_heavy = 1; strictm = 1; loose = 0;
                }
            } else {
                const float thr = uk * selcdf;
                int cnt_t = 0;
                if (tid < len       && sm->cdfa[xmin + tid]       < thr) cnt_t++;
                if (tid + TPB < len && sm->cdfa[xmin + tid + TPB] < thr) cnt_t++;
                const int wsum = __reduce_add_sync(FULLMASK, cnt_t);
                if (lane == 0) sm->cnt[warp] = wsum;
                __syncthreads();
                int tot = 0;
#pragma unroll
                for (int i = 0; i < 8; i++) tot += sm->cnt[i];
                pos = xmin + tot;
                if (pos > jend - 1) pos = jend - 1;
                break;
            }
        }

        if (tid == 0) {
            out[k]      = (float)pos;       // positions, then cond_probs
            out[Nn + k] = sm->probs[pos];
        }
        prev = pos;
        __syncthreads();   // qarr/whist/cnt stable before next step
    }
}

extern "C" void kernel_launch(void* const* d_in, const int* in_sizes, int n_in,
                              void* d_out, int out_size)
{
    (void)in_sizes; (void)n_in; (void)out_size;
    const float* eig = (const float*)d_in[0];   // eigfunc (384,384) f32
    const float* uu  = (const float*)d_in[1];   // u (96,) f32
    float* out = (float*)d_out;                 // [positions(96); cond_probs(96)]

    cudaFuncSetAttribute(sds_kernel,
                         cudaFuncAttributeMaxDynamicSharedMemorySize,
                         (int)sizeof(Smem));
    sds_kernel<<<1, TPB, sizeof(Smem)>>>(eig, uu, out);
}

// round 16
// speedup vs baseline: 1.1621x; 1.1621x over previous
#include <cuda_runtime.h>
#include <math.h>

#define Dn 384
#define Nn 96
#define TPB 256
#define FULLMASK 0xffffffffu

// Per-site chain vectors w_j = C_{j-1} v_j (current epoch), L2-resident.
__device__ float whist_g[Dn][Nn];

// Dynamic shared memory (~152 KB).
struct Smem {
    float P[Dn * Nn];                 // eigfunc[:, :96] row-major [site][comp]
    float qarr[Dn];                   // per-site pivot complement q (cur epoch)
    float probs[Dn];                  // window probs (current step)
    float cdfa[Dn];                   // running cdf (current step)
    __align__(16) float w[2][2 * Nn]; // heavy: [buf][ w1(96) | w2(96) ]
    __align__(16) float qpb[2][96];   // heavy: [buf][ q1p | sp | q2p ] x32
    __align__(16) float gfin[Nn];     // light: final correction vector
    float delta_s;
    float runF_s, cdfF_s;             // light: run/cdf carried to F
    float arl_s, cdfl_s, cdfs_s;      // loose/strict exit records
    int   jl_s, js_s, exl_s, exs_s;
    int   cnt[8];
};

__device__ __forceinline__ float grcp(float x) {
    return (fabsf(x) > 1e-30f) ? __frcp_rn(x) : 0.0f;
}

__device__ __forceinline__ void load12(const float* src, float d[12]) {
    const float4* s4 = reinterpret_cast<const float4*>(src);
    float4 a = s4[0], b = s4[1], c = s4[2];
    d[0]=a.x; d[1]=a.y; d[2]=a.z; d[3]=a.w;
    d[4]=b.x; d[5]=b.y; d[6]=b.z; d[7]=b.w;
    d[8]=c.x; d[9]=c.y; d[10]=c.z; d[11]=c.w;
}

// Deterministic fixed-order sum of 32 floats (16B-aligned smem).
__device__ __forceinline__ float sum32(const float* q) {
    const float4* q4 = reinterpret_cast<const float4*>(q);
    float t[8];
#pragma unroll
    for (int i = 0; i < 8; i++) {
        float4 v = q4[i];
        t[i] = (v.x + v.y) + (v.z + v.w);
    }
    return ((t[0]+t[1]) + (t[2]+t[3])) + ((t[4]+t[5]) + (t[6]+t[7]));
}

// Balanced 12-term dot (4 accumulators), fixed order.
__device__ __forceinline__ float dot12(const float* c, const float v[12]) {
    float a = c[0]*v[0]; a = fmaf(c[4], v[4], a); a = fmaf(c[8],  v[8],  a);
    float b = c[1]*v[1]; b = fmaf(c[5], v[5], b); b = fmaf(c[9],  v[9],  b);
    float d = c[2]*v[2]; d = fmaf(c[6], v[6], d); d = fmaf(c[10], v[10], d);
    float e = c[3]*v[3]; e = fmaf(c[7], v[7], e); e = fmaf(c[11], v[11], e);
    return (a + b) + (d + e);
}

__device__ __forceinline__ float bfly5(float a) {
#pragma unroll
    for (int off = 16; off; off >>= 1)
        a += __shfl_xor_sync(FULLMASK, a, off);
    return a;
}

// One butterfly round for 10 values (5 levels, pipelined).
__device__ __forceinline__ void bfly10(float& d0, float& d1, float& d2,
                                       float& d3, float& d4, float& d5,
                                       float& d6, float& d7, float& d8,
                                       float& d9) {
#pragma unroll
    for (int off = 16; off; off >>= 1) {
        d0 += __shfl_xor_sync(FULLMASK, d0, off);
        d1 += __shfl_xor_sync(FULLMASK, d1, off);
        d2 += __shfl_xor_sync(FULLMASK, d2, off);
        d3 += __shfl_xor_sync(FULLMASK, d3, off);
        d4 += __shfl_xor_sync(FULLMASK, d4, off);
        d5 += __shfl_xor_sync(FULLMASK, d5, off);
        d6 += __shfl_xor_sync(FULLMASK, d6, off);
        d7 += __shfl_xor_sync(FULLMASK, d7, off);
        d8 += __shfl_xor_sync(FULLMASK, d8, off);
        d9 += __shfl_xor_sync(FULLMASK, d9, off);
    }
}

// ---------------------------------------------------------------------------
// Light pass (warp 0 only; lane l owns components 3l..3l+2).
// Quad-batched epoch propagation, R14 arithmetic, but with STATIC register
// buffers (no runtime buffer index -> no local-memory spill).
// ---------------------------------------------------------------------------

// load quad of (w, q, ip) for sites BASE..BASE+3 into named buffer.
#define LPQ_LOAD(W, Q, IP, BASE) do {                                        \
    W[0][0] = whist_g[(BASE)  ][b0+0]; W[0][1] = whist_g[(BASE)  ][b0+1];    \
    W[0][2] = whist_g[(BASE)  ][b0+2];                                       \
    W[1][0] = whist_g[(BASE)+1][b0+0]; W[1][1] = whist_g[(BASE)+1][b0+1];    \
    W[1][2] = whist_g[(BASE)+1][b0+2];                                       \
    W[2][0] = whist_g[(BASE)+2][b0+0]; W[2][1] = whist_g[(BASE)+2][b0+1];    \
    W[2][2] = whist_g[(BASE)+2][b0+2];                                       \
    W[3][0] = whist_g[(BASE)+3][b0+0]; W[3][1] = whist_g[(BASE)+3][b0+1];    \
    W[3][2] = whist_g[(BASE)+3][b0+2];                                       \
    Q[0] = sm->qarr[(BASE)  ];  Q[1] = sm->qarr[(BASE)+1];                   \
    Q[2] = sm->qarr[(BASE)+2];  Q[3] = sm->qarr[(BASE)+3];                   \
    IP[0] = grcp(1.0f - Q[0]);  IP[1] = grcp(1.0f - Q[1]);                   \
    IP[2] = grcp(1.0f - Q[2]);  IP[3] = grcp(1.0f - Q[3]);                   \
} while (0)

// per-site bookkeeping (replicated scalars; lane 0 writes)
#define LPQ_BK(QN, S) do {                                                   \
    float prob = run * (QN);                                                 \
    if (!(fabsf(prob) > 1e-15f)) prob = 0.0f;                                \
    cdf += prob;                                                             \
    run *= (1.0f - (QN));                                                    \
    if (l == 0) { sm->probs[j+(S)] = prob; sm->cdfa[j+(S)] = cdf; }          \
    const float ar_ = fabsf(run);                                            \
    if (!exs && ar_ < 3e-9f * cdf) { exs = 1; js = j + (S) + 1; cdfs = cdf; }\
    if (!exl && (uk * (cdf + ar_) < cdf * (1.0f - 1e-4f)) &&                 \
        (ar_ < 3e-4f * cdf)) { exl = 1; jl = j+(S)+1; arl = ar_; cdfl = cdf; }\
    if (l == 0) sm->qarr[j+(S)] = (QN);                                      \
} while (0)

// process quad (j..j+3) from named buffer.  R14 arithmetic, verbatim.
#define LPQ_PROC(W, Q, IP) do {                                              \
    const float* vp0 = &sm->P[(j  ) * Nn + b0];                              \
    const float* vp1 = &sm->P[(j+1) * Nn + b0];                              \
    const float* vp2 = &sm->P[(j+2) * Nn + b0];                              \
    const float* vp3 = &sm->P[(j+3) * Nn + b0];                              \
    const float v00=vp0[0], v01=vp0[1], v02=vp0[2];                          \
    const float v10=vp1[0], v11=vp1[1], v12=vp1[2];                          \
    const float v20=vp2[0], v21=vp2[1], v22=vp2[2];                          \
    const float v30=vp3[0], v31=vp3[1], v32=vp3[2];                          \
    float d0 = g0*v00 + g1*v01 + g2*v02;                                     \
    float d1 = g0*v10 + g1*v11 + g2*v12;                                     \
    float d2 = g0*v20 + g1*v21 + g2*v22;                                     \
    float d3 = g0*v30 + g1*v31 + g2*v32;                                     \
    float d4 = W[0][0]*v10 + W[0][1]*v11 + W[0][2]*v12;                      \
    float d5 = W[0][0]*v20 + W[0][1]*v21 + W[0][2]*v22;                      \
    float d6 = W[0][0]*v30 + W[0][1]*v31 + W[0][2]*v32;                      \
    float d7 = W[1][0]*v20 + W[1][1]*v21 + W[1][2]*v22;                      \
    float d8 = W[1][0]*v30 + W[1][1]*v31 + W[1][2]*v32;                      \
    float d9 = W[2][0]*v30 + W[2][1]*v31 + W[2][2]*v32;                      \
    bfly10(d0,d1,d2,d3,d4,d5,d6,d7,d8,d9);                                   \
    const float e0 = d0;                         const float t0 = e0*IP[0];  \
    const float e1 = d1 + t0*d4;                 const float t1 = e1*IP[1];  \
    const float e2 = d2 + t0*d5 + t1*d7;         const float t2 = e2*IP[2];  \
    const float e3 = d3 + t0*d6 + t1*d8 + t2*d9; const float t3 = e3*IP[3];  \
    const float c0 = delta*e0; const float q0n = Q[0] + e0*c0;               \
    delta = delta * (1.0f - Q[0]) * grcp(1.0f - q0n);                        \
    const float c1 = delta*e1; const float q1n = Q[1] + e1*c1;               \
    delta = delta * (1.0f - Q[1]) * grcp(1.0f - q1n);                        \
    const float c2 = delta*e2; const float q2n = Q[2] + e2*c2;               \
    delta = delta * (1.0f - Q[2]) * grcp(1.0f - q2n);                        \
    const float c3 = delta*e3; const float q3n = Q[3] + e3*c3;               \
    delta = delta * (1.0f - Q[3]) * grcp(1.0f - q3n);                        \
    whist_g[j][b0+0] = W[0][0] + c0*g0;                                      \
    whist_g[j][b0+1] = W[0][1] + c0*g1;                                      \
    whist_g[j][b0+2] = W[0][2] + c0*g2;                                      \
    g0 += t0*W[0][0]; g1 += t0*W[0][1]; g2 += t0*W[0][2];                    \
    whist_g[j+1][b0+0] = W[1][0] + c1*g0;                                    \
    whist_g[j+1][b0+1] = W[1][1] + c1*g1;                                    \
    whist_g[j+1][b0+2] = W[1][2] + c1*g2;                                    \
    g0 += t1*W[1][0]; g1 += t1*W[1][1]; g2 += t1*W[1][2];                    \
    whist_g[j+2][b0+0] = W[2][0] + c2*g0;                                    \
    whist_g[j+2][b0+1] = W[2][1] + c2*g1;                                    \
    whist_g[j+2][b0+2] = W[2][2] + c2*g2;                                    \
    g0 += t2*W[2][0]; g1 += t2*W[2][1]; g2 += t2*W[2][2];                    \
    whist_g[j+3][b0+0] = W[3][0] + c3*g0;                                    \
    whist_g[j+3][b0+1] = W[3][1] + c3*g1;                                    \
    whist_g[j+3][b0+2] = W[3][2] + c3*g2;                                    \
    g0 += t3*W[3][0]; g1 += t3*W[3][1]; g2 += t3*W[3][2];                    \
    if (fabsf(delta) < 1e-10f && delta != 0.0f) {                            \
        delta *= 16777216.0f;                                                \
        g0 *= 2.44140625e-4f; g1 *= 2.44140625e-4f; g2 *= 2.44140625e-4f;    \
    }                                                                        \
    LPQ_BK(q0n, 0); LPQ_BK(q1n, 1); LPQ_BK(q2n, 2); LPQ_BK(q3n, 3);          \
} while (0)

__device__ void light_pass(Smem* __restrict__ sm, int xmin, int F, int pos,
                           float uk)
{
    const int l  = threadIdx.x & 31;
    const int b0 = 3 * l;
    float g0 = whist_g[pos][b0+0];
    float g1 = whist_g[pos][b0+1];
    float g2 = whist_g[pos][b0+2];
    const float qp = sm->qarr[pos];
    float delta = -(grcp(qp) + grcp(1.0f - qp));
    float run = 1.0f, cdf = 0.0f;
    int exl = 0, jl = F, exs = 0, js = F;
    float arl = 0.0f, cdfl = 0.0f, cdfs = 0.0f;
    int j = xmin;

    // two statically-named register buffers (ping-pong, no runtime index)
    float wA[4][3], qA[4], ipA[4];
    float wB[4][3], qB[4], ipB[4];

    if (j + 3 < F) LPQ_LOAD(wA, qA, ipA, j);
    while (j + 3 < F) {
        if (j + 7 < F) LPQ_LOAD(wB, qB, ipB, j + 4);
        LPQ_PROC(wA, qA, ipA);
        j += 4;
        if (j + 3 >= F) break;
        if (j + 7 < F) LPQ_LOAD(wA, qA, ipA, j + 4);
        LPQ_PROC(wB, qB, ipB);
        j += 4;
    }

    // tail: single-site path (<= 3 sites), loads directly
    while (j < F) {
        const float w0 = whist_g[j][b0+0];
        const float w1 = whist_g[j][b0+1];
        const float w2 = whist_g[j][b0+2];
        const float qa = sm->qarr[j];
        const float* vp = &sm->P[j * Nn + b0];
        float e = g0*vp[0] + g1*vp[1] + g2*vp[2];
        e = bfly5(e);
        const float c  = delta * e;
        const float qn = qa + e * c;
        whist_g[j][b0+0] = w0 + c*g0;
        whist_g[j][b0+1] = w1 + c*g1;
        whist_g[j][b0+2] = w2 + c*g2;
        const float t = e * grcp(1.0f - qa);
        g0 += t*w0; g1 += t*w1; g2 += t*w2;
        delta = delta * (1.0f - qa) * grcp(1.0f - qn);
        float prob = run * qn;
        if (!(fabsf(prob) > 1e-15f)) prob = 0.0f;
        cdf += prob;
        run *= (1.0f - qn);
        if (l == 0) { sm->probs[j] = prob; sm->cdfa[j] = cdf; }
        const float ar = fabsf(run);
        if (!exs && ar < 3e-9f * cdf) { exs = 1; js = j + 1; cdfs = cdf; }
        if (!exl && (uk * (cdf + ar) < cdf * (1.0f - 1e-4f)) &&
            (ar < 3e-4f * cdf)) { exl = 1; jl = j + 1; arl = ar; cdfl = cdf; }
        if (l == 0) sm->qarr[j] = qn;
        j++;
    }

    // publish correction + scan scalars
    sm->gfin[b0+0] = g0; sm->gfin[b0+1] = g1; sm->gfin[b0+2] = g2;
    if (l == 0) {
        sm->delta_s = delta;
        sm->runF_s = run;  sm->cdfF_s = cdf;
        sm->exl_s = exl; sm->jl_s = jl; sm->arl_s = arl; sm->cdfl_s = cdfl;
        sm->exs_s = exs; sm->js_s = js; sm->cdfs_s = cdfs;
    }
}

// ---------------------------------------------------------------------------
// Heavy scan produce helpers (frontier sites; full matvec + reductions).
// Tiling: rt = tid>>3 (rows 3rt..3rt+2), ct = tid&7 (cols 12ct..12ct+11).
// ---------------------------------------------------------------------------
__device__ __forceinline__ void produce1(Smem* __restrict__ sm,
                                         const float C[3][12], float p1[3],
                                         int j, int buf, int rt, int ct)
{
    float v[12];
    load12(&sm->P[j * Nn + 12 * ct], v);
    p1[0] = dot12(C[0], v);
    p1[1] = dot12(C[1], v);
    p1[2] = dot12(C[2], v);
#pragma unroll
    for (int off = 1; off < 8; off <<= 1) {
        p1[0] += __shfl_xor_sync(FULLMASK, p1[0], off);
        p1[1] += __shfl_xor_sync(FULLMASK, p1[1], off);
        p1[2] += __shfl_xor_sync(FULLMASK, p1[2], off);
    }
    const float* vr = &sm->P[j * Nn + 3 * rt];
    const float qp = vr[0]*p1[0] + vr[1]*p1[1] + vr[2]*p1[2];
    if (ct == 0) {
        sm->w[buf][3*rt+0] = p1[0];
        sm->w[buf][3*rt+1] = p1[1];
        sm->w[buf][3*rt+2] = p1[2];
        sm->qpb[buf][rt] = qp;
    }
}

__device__ __forceinline__ void produce2(Smem* __restrict__ sm,
                                         const float C[3][12],
                                         float p1[3], float p2[3],
                                         int j, int buf, int rt, int ct)
{
    float v1[12], v2[12];
    load12(&sm->P[j * Nn + 12 * ct], v1);
    load12(&sm->P[(j + 1) * Nn + 12 * ct], v2);
#pragma unroll
    for (int a = 0; a < 3; a++) {
        p1[a] = dot12(C[a], v1);
        p2[a] = dot12(C[a], v2);
    }
#pragma unroll
    for (int off = 1; off < 8; off <<= 1) {
        p1[0] += __shfl_xor_sync(FULLMASK, p1[0], off);
        p1[1] += __shfl_xor_sync(FULLMASK, p1[1], off);
        p1[2] += __shfl_xor_sync(FULLMASK, p1[2], off);
        p2[0] += __shfl_xor_sync(FULLMASK, p2[0], off);
        p2[1] += __shfl_xor_sync(FULLMASK, p2[1], off);
        p2[2] += __shfl_xor_sync(FULLMASK, p2[2], off);
    }
    const float* vr1 = &sm->P[j * Nn + 3 * rt];
    const float* vr2 = &sm->P[(j + 1) * Nn + 3 * rt];
    const float q1p = vr1[0]*p1[0] + vr1[1]*p1[1] + vr1[2]*p1[2];
    const float sp  = vr2[0]*p1[0] + vr2[1]*p1[1] + vr2[2]*p1[2];
    const float q2p = vr2[0]*p2[0] + vr2[1]*p2[1] + vr2[2]*p2[2];
    if (ct == 0) {
        sm->w[buf][3*rt+0]    = p1[0];
        sm->w[buf][3*rt+1]    = p1[1];
        sm->w[buf][3*rt+2]    = p1[2];
        sm->w[buf][Nn+3*rt+0] = p2[0];
        sm->w[buf][Nn+3*rt+1] = p2[1];
        sm->w[buf][Nn+3*rt+2] = p2[2];
        sm->qpb[buf][rt]      = q1p;
        sm->qpb[buf][32 + rt] = sp;
        sm->qpb[buf][64 + rt] = q2p;
    }
}

// Heavy frontier scan from jstart with dual stop. Updates run/cdf in place.
// All control scalars replicated across threads (uniform barriers).
__device__ __forceinline__ void heavy_scan(Smem* __restrict__ sm,
    float (&cw)[3][12], int jstart, int xmax, float& run, float& cdf,
    int strict, float uk, int rt, int ct, int tid,
    int& jend_out, int& by_loose_out)
{
    if (jstart >= xmax) { jend_out = jstart; by_loose_out = 0; return; }
    int buf = 0;
    int j = jstart;
    int nb = (xmax - j >= 2) ? 2 : 1;
    float p1[3], p2[3];
    if (nb == 2) produce2(sm, cw, p1, p2, j, buf, rt, ct);
    else         produce1(sm, cw, p1, j, buf, rt, ct);
    for (;;) {
        __syncthreads();
        if (nb == 2) {
            float wc1[12], wc2[12];
            load12(&sm->w[buf][12 * ct], wc1);
            load12(&sm->w[buf][Nn + 12 * ct], wc2);
            const float q1  = sum32(&sm->qpb[buf][0]);
            const float s   = sum32(&sm->qpb[buf][32]);
            const float q2r = sum32(&sm->qpb[buf][64]);
            const float inv1 = grcp(1.0f - q1);
            const float t = inv1 * s;
            const float q2 = q2r + t * s;      // Schur-corrected
            const float inv2 = grcp(1.0f - q2);
            float p2c[3], wc2c[12];
#pragma unroll
            for (int a = 0; a < 3; a++) p2c[a] = p2[a] + t * p1[a];
#pragma unroll
            for (int b = 0; b < 12; b++) wc2c[b] = wc2[b] + t * wc1[b];

            if (ct == 0) {
#pragma unroll
                for (int a = 0; a < 3; a++) {
                    whist_g[j][3*rt+a]   = p1[a];
                    whist_g[j+1][3*rt+a] = p2c[a];
                }
            }
            if (tid == 0) { sm->qarr[j] = q1; sm->qarr[j+1] = q2; }
#pragma unroll
            for (int a = 0; a < 3; a++) {
                const float u1 = p1[a]  * inv1;
                const float u2 = p2c[a] * inv2;
#pragma unroll
                for (int b = 0; b < 12; b++) {
                    cw[a][b] += u1 * wc1[b];
                    cw[a][b] += u2 * wc2c[b];
                }
            }
            float prob = run * q1;
            if (!(fabsf(prob) > 1e-15f)) prob = 0.0f;
            cdf += prob;
            if (tid == 0) { sm->probs[j] = prob; sm->cdfa[j] = cdf; }
            run *= (1.0f - q1);
            prob = run * q2;
            if (!(fabsf(prob) > 1e-15f)) prob = 0.0f;
            cdf += prob;
            if (tid == 0) { sm->probs[j+1] = prob; sm->cdfa[j+1] = cdf; }
            run *= (1.0f - q2);
        } else {
            float wc1[12];
            load12(&sm->w[buf][12 * ct], wc1);
            const float q1 = sum32(&sm->qpb[buf][0]);
            const float inv1 = grcp(1.0f - q1);
            if (ct == 0) {
#pragma unroll
                for (int a = 0; a < 3; a++)
                    whist_g[j][3*rt+a] = p1[a];
            }
            if (tid == 0) sm->qarr[j] = q1;
#pragma unroll
            for (int a = 0; a < 3; a++) {
                const float t = p1[a] * inv1;
#pragma unroll
                for (int b = 0; b < 12; b++) cw[a][b] += t * wc1[b];
            }
            float prob = run * q1;
            if (!(fabsf(prob) > 1e-15f)) prob = 0.0f;
            cdf += prob;
            if (tid == 0) { sm->probs[j] = prob; sm->cdfa[j] = cdf; }
            run *= (1.0f - q1);
        }

        const int jn = j + nb;
        const float ar = fabsf(run);
        const bool stop_s = (ar < 3e-9f * cdf);
        bool stop_l = false;
        if (!strict)
            stop_l = ((uk * (cdf + ar) < cdf * (1.0f - 1e-4f)) &&
                      (ar < 3e-4f * cdf));
        if (stop_s || stop_l || jn >= xmax) {
            jend_out = jn;
            by_loose_out = (stop_l && !stop_s && jn < xmax) ? 1 : 0;
            break;
        }
        const int nb2 = (xmax - jn >= 2) ? 2 : 1;
        if (nb2 == 2) produce2(sm, cw, p1, p2, jn, buf ^ 1, rt, ct);
        else          produce1(sm, cw, p1, jn, buf ^ 1, rt, ct);
        buf ^= 1; j = jn; nb = nb2;
    }
}

__global__ void __launch_bounds__(TPB, 1)
sds_kernel(const float* __restrict__ eig, const float* __restrict__ u,
           float* __restrict__ out)
{
    extern __shared__ unsigned char smraw[];
    Smem* sm = reinterpret_cast<Smem*>(smraw);
    const int tid  = threadIdx.x;
    const int lane = tid & 31;
    const int warp = tid >> 5;
    const int rt   = tid >> 3;   // rows 3rt..3rt+2
    const int ct   = tid & 7;    // cols 12ct..12ct+11

    // Load P = eigfunc[:, :96] (first 96 of each 384-row).
    for (int idx = tid; idx < Dn * Nn; idx += TPB) {
        const int r = idx / Nn, c = idx - r * Nn;
        sm->P[idx] = eig[r * Dn + c];
    }

    // Persistent speculative frontier state cw (all of [0,F) empty). Starts I.
    float cw[3][12];
#pragma unroll
    for (int a = 0; a < 3; a++)
#pragma unroll
        for (int b = 0; b < 12; b++)
            cw[a][b] = (3 * rt + a == 12 * ct + b) ? 1.0f : 0.0f;

    __syncthreads();

    int prev = -1;
    int F = 0;   // frontier: sites [0, F) have current-epoch stored (q, w)
    for (int k = 0; k < Nn; k++) {
        const int xmin = prev + 1;
        const int xmax = Dn - Nn + k + 1;   // exclusive
        const float uk = u[k];

        float runF, cdfF, arl = 0.0f, cdfl = 0.0f, cdfs = 0.0f;
        int exl, exs, jl = F, js = F;

        if (k > 0) {
            if (warp == 0) light_pass(sm, xmin, F, prev, uk);
            __syncthreads();
            // materialize the correction into cw: cw += delta * g g^T
            const float dlt = sm->delta_s;
            const float gr0 = sm->gfin[3*rt+0];
            const float gr1 = sm->gfin[3*rt+1];
            const float gr2 = sm->gfin[3*rt+2];
            float gc[12];
            load12(&sm->gfin[12*ct], gc);
            const float t0 = dlt * gr0, t1 = dlt * gr1, t2 = dlt * gr2;
#pragma unroll
            for (int b = 0; b < 12; b++) {
                cw[0][b] += t0 * gc[b];
                cw[1][b] += t1 * gc[b];
                cw[2][b] += t2 * gc[b];
            }
            runF = sm->runF_s; cdfF = sm->cdfF_s;
            exl = sm->exl_s; jl = sm->jl_s; arl = sm->arl_s; cdfl = sm->cdfl_s;
            exs = sm->exs_s; js = sm->js_s; cdfs = sm->cdfs_s;
        } else {
            runF = 1.0f; cdfF = 0.0f; exl = 0; exs = 0;
        }

        // ---- determine selection window (loose-first, verified) ----
        int jend; float selcdf, selar = 0.0f; int loose;
        int need_heavy, strictm = 0;
        float hrun = runF, hcdf = cdfF;
        const int from_light_loose = exl;
        if (exl)      { jend = jl; selcdf = cdfl; selar = arl; loose = 1; need_heavy = 0; }
        else if (exs) { jend = js; selcdf = cdfs; loose = 0; need_heavy = 0; }
        else          { need_heavy = 1; loose = 0; jend = F; selcdf = cdfF; }

        int pos = -1;
        for (int attempt = 0; attempt < 2; attempt++) {
            if (need_heavy) {
                int je, bl;
                heavy_scan(sm, cw, F, xmax, hrun, hcdf, strictm, uk,
                           rt, ct, tid, je, bl);
                jend = je; F = je;
                selcdf = hcdf; selar = fabsf(hrun); loose = bl;
                need_heavy = 0;
            }
            __syncthreads();   // probs/cdfa visible; orders cnt reuse

            const int len = jend - xmin;        // <= 289 (2 elems/thread)
            if (loose) {
                const float thr_mid = uk * selcdf;
                const float thr_lo  = thr_mid * (1.0f - 3e-6f);
                const float thr_hi  = uk * (selcdf + selar) * (1.0f + 3e-6f);
                int packed = 0;
                if (tid < len) {
                    const float cv = sm->cdfa[xmin + tid];
                    packed += (cv < thr_lo ? 1 : 0)
                            + ((cv < thr_mid ? 1 : 0) << 10)
                            + ((cv < thr_hi ? 1 : 0) << 20);
                }
                if (tid + TPB < len) {
                    const float cv = sm->cdfa[xmin + tid + TPB];
                    packed += (cv < thr_lo ? 1 : 0)
                            + ((cv < thr_mid ? 1 : 0) << 10)
                            + ((cv < thr_hi ? 1 : 0) << 20);
                }
                const int wsum = __reduce_add_sync(FULLMASK, packed);
                if (lane == 0) sm->cnt[warp] = wsum;
                __syncthreads();
                int tot = 0;
#pragma unroll
                for (int i = 0; i < 8; i++) tot += sm->cnt[i];
                const int c_lo  = tot & 1023;
                const int c_hi  = (tot >> 20) & 1023;
                int p_lo = xmin + c_lo;  if (p_lo > jend - 1) p_lo = jend - 1;
                int p_hi = xmin + c_hi;  if (p_hi > jend - 1) p_hi = jend - 1;
                if (p_lo == p_hi) { pos = p_lo; break; }
                // ambiguous: fall back to strict
                if (from_light_loose && exs) {
                    jend = js; selcdf = cdfs; loose = 0; need_heavy = 0;
                } else {
                    // resume heavy with strict stop (hrun/hcdf hold state at F)
                    need_heavy = 1; strictm = 1; loose = 0;
                }
            } else {
                const float thr = uk * selcdf;
                int cnt_t = 0;
                if (tid < len       && sm->cdfa[xmin + tid]       < thr) cnt_t++;
                if (tid + TPB < len && sm->cdfa[xmin + tid + TPB] < thr) cnt_t++;
                const int wsum = __reduce_add_sync(FULLMASK, cnt_t);
                if (lane == 0) sm->cnt[warp] = wsum;
                __syncthreads();
                int tot = 0;
#pragma unroll
                for (int i = 0; i < 8; i++) tot += sm->cnt[i];
                pos = xmin + tot;
                if (pos > jend - 1) pos = jend - 1;
                break;
            }
        }

        if (tid == 0) {
            out[k]      = (float)pos;       // positions, then cond_probs
            out[Nn + k] = sm->probs[pos];
        }
        prev = pos;
        __syncthreads();   // qarr/whist/cnt stable before next step
    }
}

extern "C" void kernel_launch(void* const* d_in, const int* in_sizes, int n_in,
                              void* d_out, int out_size)
{
    (void)in_sizes; (void)n_in; (void)out_size;
    const float* eig = (const float*)d_in[0];   // eigfunc (384,384) f32
    const float* uu  = (const float*)d_in[1];   // u (96,) f32
    float* out = (float*)d_out;                 // [positions(96); cond_probs(96)]

    cudaFuncSetAttribute(sds_kernel,
                         cudaFuncAttributeMaxDynamicSharedMemorySize,
                         (int)sizeof(Smem));
    sds_kernel<<<1, TPB, sizeof(Smem)>>>(eig, uu, out);
}